// round 5
// baseline (speedup 1.0000x reference)
#include <cuda_runtime.h>
#include <cstdint>

#define NCOLS            696     // 16 + 120 + 560
#define ROWS_PER_WARP    32
#define WARPS_PER_BLOCK  4
#define THREADS          128
#define MIN_BLOCKS       3
#define ROW_STRIDE       68      // 64 data words + 4 pad (conflict-free STS.128; rows contiguous 256B)
#define BUF_FLOATS       (ROWS_PER_WARP * ROW_STRIDE)   // 2176 floats = 8704 B
// per block: 4 warps * 2 buffers * 8704 B = 69,632 B dynamic smem

// Dubois t-norm for a,b >= 0:  a*b / max(max(a,b), lambda) == min(a, b, a*b/lambda)
__device__ __forceinline__ float tnorm(float a, float b, float inv_l) {
    return fminf(fminf(a, b), a * b * inv_l);
}

__device__ __forceinline__ uint32_t smem_u32(const void* p) {
    return (uint32_t)__cvta_generic_to_shared(p);
}

// Pack values for columns [LO,HI) of this lane's row into its warp buffer row
// (wbuf[lane*ROW_STRIDE + (col-LO)]) using STS.128 every 4 columns.
// col/rel are compile-time constants; out-of-range work is DCE'd.
template<int LO, int HI>
__device__ __forceinline__ void compute_chunk(const float xv[16], float inv_l,
                                              float* __restrict__ wbuf, int lane) {
    float4 acc;
    float* rowp = wbuf + lane * ROW_STRIDE;

    int col = 0;
    #define EMIT(VAL)                                                           \
        do {                                                                    \
            if (col >= LO && col < HI) {                                        \
                int rel = col - LO;                                             \
                if ((rel & 3) == 0) acc.x = (VAL);                              \
                else if ((rel & 3) == 1) acc.y = (VAL);                         \
                else if ((rel & 3) == 2) acc.z = (VAL);                         \
                else {                                                          \
                    acc.w = (VAL);                                              \
                    *reinterpret_cast<float4*>(rowp + (rel - 3)) = acc;         \
                }                                                               \
            }                                                                   \
            col++;                                                              \
        } while (0)

    #pragma unroll
    for (int i = 0; i < 16; i++) EMIT(xv[i]);                    // singles 0..15

    #pragma unroll
    for (int i = 0; i < 16; i++) {                               // pairs 16..135
        #pragma unroll
        for (int j = i + 1; j < 16; j++) EMIT(tnorm(xv[i], xv[j], inv_l));
    }

    #pragma unroll
    for (int i = 0; i < 16; i++) {                               // triples 136..695
        #pragma unroll
        for (int j = i + 1; j < 16; j++) {
            float p = tnorm(xv[i], xv[j], inv_l);                // dead if no k in range
            #pragma unroll
            for (int k = j + 1; k < 16; k++) EMIT(tnorm(p, xv[k], inv_l));
        }
    }
    #undef EMIT
}

// Lane 0 only: TMA bulk-store this warp's 32 staged rows for columns [LO,HI).
// Each row: contiguous (HI-LO)*4 bytes in smem -> strided destination in gmem.
template<int LO, int HI>
__device__ __forceinline__ void bulk_store_chunk(const float* __restrict__ wbuf,
                                                 float* __restrict__ out,
                                                 int wrow0) {
    constexpr int NBYTES = (HI - LO) * 4;          // 256 or 224, multiple of 16
    float* gbase = out + (size_t)wrow0 * NCOLS + LO;
    #pragma unroll
    for (int r = 0; r < ROWS_PER_WARP; r++) {
        uint32_t src = smem_u32(wbuf + r * ROW_STRIDE);
        asm volatile(
            "cp.async.bulk.global.shared::cta.bulk_group [%0], [%1], %2;"
            :: "l"(gbase + (size_t)r * NCOLS), "r"(src), "n"(NBYTES)
            : "memory");
    }
}

__device__ __forceinline__ void bulk_commit() {
    asm volatile("cp.async.bulk.commit_group;" ::: "memory");
}
template<int N>
__device__ __forceinline__ void bulk_wait_read() {
    asm volatile("cp.async.bulk.wait_group.read %0;" :: "n"(N) : "memory");
}
__device__ __forceinline__ void fence_async_smem() {
    asm volatile("fence.proxy.async.shared::cta;" ::: "memory");
}

__global__ void __launch_bounds__(THREADS, MIN_BLOCKS)
dubois_kernel(const float* __restrict__ x,
              const float* __restrict__ lambda_,
              float* __restrict__ out) {
    extern __shared__ float smem[];

    const int lane = threadIdx.x & 31;
    const int wid  = threadIdx.x >> 5;
    float* bufA = smem + wid * 2 * BUF_FLOATS;
    float* bufB = bufA + BUF_FLOATS;

    const int wrow0 = blockIdx.x * (ROWS_PER_WARP * WARPS_PER_BLOCK) + wid * ROWS_PER_WARP;
    const int row   = wrow0 + lane;

    const float inv_l = 1.0f / __ldg(lambda_);

    // Load this lane's 16 inputs into registers (4x LDG.128).
    float xv[16];
    const float4* xp = reinterpret_cast<const float4*>(x) + (size_t)row * 4;
    float4 a = xp[0], b = xp[1], c = xp[2], d = xp[3];
    xv[0]=a.x;  xv[1]=a.y;  xv[2]=a.z;  xv[3]=a.w;
    xv[4]=b.x;  xv[5]=b.y;  xv[6]=b.z;  xv[7]=b.w;
    xv[8]=c.x;  xv[9]=c.y;  xv[10]=c.z; xv[11]=c.w;
    xv[12]=d.x; xv[13]=d.y; xv[14]=d.z; xv[15]=d.w;

    // Software pipeline, per-warp double buffer. Chunk s is computed at step s
    // (even -> bufA, odd -> bufB) and bulk-stored by lane 0 at step s+1.
    // wait_group.read<1> after commit guarantees the group two chunks back
    // (same buffer parity as the upcoming compute) has finished reading smem.
    compute_chunk<0, 64>(xv, inv_l, bufA, lane);

#define STEP(PLO, PHI, CLO, CHI, WB, CB)                          \
    __syncwarp();                                                 \
    if (lane == 0) {                                              \
        fence_async_smem();                                       \
        bulk_store_chunk<PLO, PHI>(WB, out, wrow0);               \
        bulk_commit();                                            \
        bulk_wait_read<1>();                                      \
    }                                                             \
    __syncwarp();                                                 \
    compute_chunk<CLO, CHI>(xv, inv_l, CB, lane);

    STEP(0,   64,  64,  128, bufA, bufB)
    STEP(64,  128, 128, 192, bufB, bufA)
    STEP(128, 192, 192, 256, bufA, bufB)
    STEP(192, 256, 256, 320, bufB, bufA)
    STEP(256, 320, 320, 384, bufA, bufB)
    STEP(320, 384, 384, 448, bufB, bufA)
    STEP(384, 448, 448, 512, bufA, bufB)
    STEP(448, 512, 512, 576, bufB, bufA)
    STEP(512, 576, 576, 640, bufA, bufB)
    STEP(576, 640, 640, 696, bufB, bufA)
#undef STEP

    __syncwarp();
    if (lane == 0) {
        fence_async_smem();
        bulk_store_chunk<640, 696>(bufA, out, wrow0);
        bulk_commit();
        // gmem visibility at kernel boundary is guaranteed; no wait needed.
    }
}

extern "C" void kernel_launch(void* const* d_in, const int* in_sizes, int n_in,
                              void* d_out, int out_size) {
    const float* x   = (const float*)d_in[0];
    const float* lam = (const float*)d_in[1];
    float* out = (float*)d_out;

    const int SMEM_BYTES = WARPS_PER_BLOCK * 2 * BUF_FLOATS * sizeof(float); // 69,632
    cudaFuncSetAttribute(dubois_kernel, cudaFuncAttributeMaxDynamicSharedMemorySize,
                         SMEM_BYTES);

    int rows = in_sizes[0] / 16;                                  // 131072
    int grid = rows / (ROWS_PER_WARP * WARPS_PER_BLOCK);          // 1024
    dubois_kernel<<<grid, THREADS, SMEM_BYTES>>>(x, lam, out);
}